// round 2
// baseline (speedup 1.0000x reference)
#include <cuda_runtime.h>
#include <cstdint>

#define N_NODES 50000
#define N_EDGES 1600000
#define NUM_FEATURES 500
#define HIDDEN 64
#define NUM_CLASSES 40
#define NUM_LAYERS 4
#define STEP_F 0.1f

// ---------------- device scratch (static, allocation-free) ----------------
__device__ float g_h[N_NODES * HIDDEN];
__device__ float g_x0[N_NODES * HIDDEN];
__device__ float g_agg[N_NODES * HIDDEN];
__device__ unsigned long long g_srccoef[N_EDGES];   // packed {src, coef}
__device__ int   g_rowptr[N_NODES + 1];
__device__ int   g_degcnt[N_NODES];
__device__ int   g_fill[N_NODES];
__device__ float g_deginv[N_NODES];
__device__ float g_W[HIDDEN * HIDDEN];

// ---------------- graph preprocessing ----------------
__global__ void zero_counts() {
    int i = blockIdx.x * blockDim.x + threadIdx.x;
    if (i < N_NODES) { g_degcnt[i] = 0; g_fill[i] = 0; }
}

__global__ void count_deg(const int* __restrict__ col) {
    int e = blockIdx.x * blockDim.x + threadIdx.x;
    if (e < N_EDGES) atomicAdd(&g_degcnt[col[e]], 1);
}

__global__ void deg_inv_kernel() {
    int i = blockIdx.x * blockDim.x + threadIdx.x;
    if (i < N_NODES) {
        int c = g_degcnt[i];
        g_deginv[i] = (c > 0) ? rsqrtf((float)c) : 0.0f;
    }
}

// single-block exclusive scan of g_degcnt -> g_rowptr (50001 entries)
__global__ void scan_kernel() {
    __shared__ int s[1024];
    __shared__ int carry_s;
    if (threadIdx.x == 0) carry_s = 0;
    __syncthreads();
    for (int base = 0; base < N_NODES; base += 1024) {
        int i = base + threadIdx.x;
        int v = (i < N_NODES) ? g_degcnt[i] : 0;
        s[threadIdx.x] = v;
        __syncthreads();
        for (int off = 1; off < 1024; off <<= 1) {
            int t = 0;
            if (threadIdx.x >= off) t = s[threadIdx.x - off];
            __syncthreads();
            if (threadIdx.x >= off) s[threadIdx.x] += t;
            __syncthreads();
        }
        if (i < N_NODES) g_rowptr[i] = carry_s + s[threadIdx.x] - v;
        __syncthreads();
        if (threadIdx.x == 0) carry_s += s[1023];
        __syncthreads();
    }
    if (threadIdx.x == 0) g_rowptr[N_NODES] = carry_s;
}

__global__ void fill_csr(const int* __restrict__ row, const int* __restrict__ col) {
    int e = blockIdx.x * blockDim.x + threadIdx.x;
    if (e >= N_EDGES) return;
    int v = col[e];
    int r = row[e];
    int slot = g_rowptr[v] + atomicAdd(&g_fill[v], 1);
    float cf = g_deginv[r] * g_deginv[v];
    g_srccoef[slot] = (unsigned long long)(unsigned)r
                    | ((unsigned long long)__float_as_uint(cf) << 32);
}

// ---------------- pairwise weight: W_eff = sym(triu(pw,1)) + diag(q*rowsum|W|+r)
__global__ void weff_kernel(const float* __restrict__ pw) {
    int i = threadIdx.x;
    if (i >= HIDDEN) return;
    float q  = pw[i * (HIDDEN + 2) + HIDDEN];
    float rr = pw[i * (HIDDEN + 2) + HIDDEN + 1];
    float s = 0.0f;
    for (int j = 0; j < HIDDEN; j++) {
        float w = 0.0f;
        if (i < j)      w = pw[i * (HIDDEN + 2) + j];
        else if (i > j) w = pw[j * (HIDDEN + 2) + i];
        s += fabsf(w);
        g_W[i * HIDDEN + j] = w;
    }
    g_W[i * HIDDEN + i] = q * s + rr;
}

// ---------------- edge aggregation: agg[v] = sum_{e: col==v} coef*h[src]
// one warp per node; 32 lanes cover the 64-float row as float2; pure gather,
// no atomics; CSR metadata broadcast-loaded; 2-edge unroll for MLP.
__global__ void gather_kernel() {
    int gw   = (blockIdx.x * blockDim.x + threadIdx.x) >> 5;
    int lane = threadIdx.x & 31;
    if (gw >= N_NODES) return;
    int beg = g_rowptr[gw];
    int end = g_rowptr[gw + 1];
    float2 acc = make_float2(0.0f, 0.0f);
    int e = beg;
    for (; e + 1 < end; e += 2) {
        unsigned long long p0 = g_srccoef[e];
        unsigned long long p1 = g_srccoef[e + 1];
        int   s0 = (int)(unsigned)(p0 & 0xffffffffull);
        int   s1 = (int)(unsigned)(p1 & 0xffffffffull);
        float c0 = __uint_as_float((unsigned)(p0 >> 32));
        float c1 = __uint_as_float((unsigned)(p1 >> 32));
        float2 v0 = *(const float2*)(g_h + (size_t)s0 * HIDDEN + lane * 2);
        float2 v1 = *(const float2*)(g_h + (size_t)s1 * HIDDEN + lane * 2);
        acc.x += c0 * v0.x; acc.y += c0 * v0.y;
        acc.x += c1 * v1.x; acc.y += c1 * v1.y;
    }
    if (e < end) {
        unsigned long long p0 = g_srccoef[e];
        int   s0 = (int)(unsigned)(p0 & 0xffffffffull);
        float c0 = __uint_as_float((unsigned)(p0 >> 32));
        float2 v0 = *(const float2*)(g_h + (size_t)s0 * HIDDEN + lane * 2);
        acc.x += c0 * v0.x; acc.y += c0 * v0.y;
    }
    *(float2*)(g_agg + (size_t)gw * HIDDEN + lane * 2) = acc;
}

// ---------------- register-tiled SGEMM: C[M,N] = A[M,K] @ B[N,K]^T, fused epilogues
// MODE 0: encoder   (A=x, B=enc_w)     -> writes g_h and g_x0
// MODE 1: layer     (A=g_agg, B=g_W)   -> g_h = g_h + STEP*relu(acc - g_h*ext + g_x0*beta)
// MODE 2: decoder   (A=g_h, B=dec_w)   -> writes Cout
#define BM 128
#define BN 64
#define BK 16
#define TM 8
#define TN 4

template <int MODE>
__global__ void gemm_nt(const float* __restrict__ Ap, const float* __restrict__ Bp,
                        float* __restrict__ Cout,
                        int M, int N, int K,
                        const float* __restrict__ ext, const float* __restrict__ betap) {
    __shared__ float As[BK][BM + 4];
    __shared__ float Bs[BK][BN + 4];

    const float* A = (MODE == 0) ? Ap : ((MODE == 1) ? (const float*)g_agg : (const float*)g_h);
    const float* B = (MODE == 1) ? (const float*)g_W : Bp;

    int tid = threadIdx.x;        // 256 threads
    int tx = tid & 15;            // 16 col groups of TN=4
    int ty = tid >> 4;            // 16 row groups of TM=8
    int bm0 = blockIdx.y * BM;

    float acc[TM][TN];
#pragma unroll
    for (int r = 0; r < TM; r++)
#pragma unroll
        for (int c = 0; c < TN; c++) acc[r][c] = 0.0f;

    for (int kb = 0; kb < K; kb += BK) {
        // A tile, stored transposed: As[k][row]
#pragma unroll
        for (int it = 0; it < 2; it++) {
            int j = tid + it * 256;           // 0..511
            int arow = j >> 2;                // 0..127
            int kc4 = (j & 3) * 4;            // 0,4,8,12
            int grow = bm0 + arow;
#pragma unroll
            for (int i = 0; i < 4; i++) {
                int gc = kb + kc4 + i;
                float v = (grow < M && gc < K) ? A[(size_t)grow * K + gc] : 0.0f;
                As[kc4 + i][arow] = v;
            }
        }
        // B tile, stored transposed: Bs[k][ncol]
        {
            int j = tid;                      // 0..255
            int nrow = j >> 2;                // 0..63
            int kc4 = (j & 3) * 4;
#pragma unroll
            for (int i = 0; i < 4; i++) {
                int gc = kb + kc4 + i;
                float v = (nrow < N && gc < K) ? B[(size_t)nrow * K + gc] : 0.0f;
                Bs[kc4 + i][nrow] = v;
            }
        }
        __syncthreads();
#pragma unroll
        for (int k = 0; k < BK; k++) {
            float4 a0 = *(const float4*)&As[k][ty * TM];
            float4 a1 = *(const float4*)&As[k][ty * TM + 4];
            float4 b  = *(const float4*)&Bs[k][tx * TN];
            float ar[TM] = {a0.x, a0.y, a0.z, a0.w, a1.x, a1.y, a1.z, a1.w};
            float bc[TN] = {b.x, b.y, b.z, b.w};
#pragma unroll
            for (int r = 0; r < TM; r++)
#pragma unroll
                for (int c = 0; c < TN; c++)
                    acc[r][c] += ar[r] * bc[c];
        }
        __syncthreads();
    }

    int col = tx * TN;
    if (col >= N) return;   // N % 4 == 0 in all uses, so whole-float4 guard is safe

    float betav = 0.0f;
    float4 extv = make_float4(0.f, 0.f, 0.f, 0.f);
    if (MODE == 1) {
        betav = betap[0];
        extv = *(const float4*)&ext[col];
    }

#pragma unroll
    for (int r = 0; r < TM; r++) {
        int row = bm0 + ty * TM + r;
        if (row >= M) continue;
        float4 o = make_float4(acc[r][0], acc[r][1], acc[r][2], acc[r][3]);
        if (MODE == 0) {
            *(float4*)&g_h[(size_t)row * HIDDEN + col]  = o;
            *(float4*)&g_x0[(size_t)row * HIDDEN + col] = o;
        } else if (MODE == 1) {
            float4 hv = *(const float4*)&g_h[(size_t)row * HIDDEN + col];
            float4 xv = *(const float4*)&g_x0[(size_t)row * HIDDEN + col];
            float4 u;
            u.x = hv.x + STEP_F * fmaxf(o.x - hv.x * extv.x + xv.x * betav, 0.0f);
            u.y = hv.y + STEP_F * fmaxf(o.y - hv.y * extv.y + xv.y * betav, 0.0f);
            u.z = hv.z + STEP_F * fmaxf(o.z - hv.z * extv.z + xv.z * betav, 0.0f);
            u.w = hv.w + STEP_F * fmaxf(o.w - hv.w * extv.w + xv.w * betav, 0.0f);
            *(float4*)&g_h[(size_t)row * HIDDEN + col] = u;
        } else {
            *(float4*)&Cout[(size_t)row * N + col] = o;
        }
    }
}

// ---------------- launch ----------------
extern "C" void kernel_launch(void* const* d_in, const int* in_sizes, int n_in,
                              void* d_out, int out_size) {
    const float* x    = (const float*)d_in[0];   // [50000, 500]
    const int*   ei   = (const int*)  d_in[1];   // [2, 1600000]
    const float* enc  = (const float*)d_in[2];   // [64, 500]
    const float* dec  = (const float*)d_in[3];   // [40, 64]
    const float* ext  = (const float*)d_in[4];   // [1, 64]
    const float* beta = (const float*)d_in[5];   // [1]
    const float* pw   = (const float*)d_in[6];   // [64, 66]
    float* out = (float*)d_out;                  // [50000, 40]

    const int* erow = ei;
    const int* ecol = ei + N_EDGES;

    // graph preprocessing (CSR by destination)
    zero_counts<<<(N_NODES + 255) / 256, 256>>>();
    count_deg<<<(N_EDGES + 255) / 256, 256>>>(ecol);
    deg_inv_kernel<<<(N_NODES + 255) / 256, 256>>>();
    scan_kernel<<<1, 1024>>>();
    fill_csr<<<(N_EDGES + 255) / 256, 256>>>(erow, ecol);
    weff_kernel<<<1, 64>>>(pw);

    dim3 grid_enc(1, (N_NODES + BM - 1) / BM);

    // encoder: h = x @ enc_w^T ; x0 = h
    gemm_nt<0><<<grid_enc, 256>>>(x, enc, nullptr, N_NODES, HIDDEN, NUM_FEATURES,
                                  nullptr, nullptr);

    // 4 propagation layers
    for (int l = 0; l < NUM_LAYERS; l++) {
        gather_kernel<<<(N_NODES * 32 + 255) / 256, 256>>>();
        gemm_nt<1><<<grid_enc, 256>>>(nullptr, nullptr, nullptr,
                                      N_NODES, HIDDEN, HIDDEN, ext, beta);
    }

    // decoder: out = h @ dec_w^T
    gemm_nt<2><<<grid_enc, 256>>>(nullptr, dec, out, N_NODES, NUM_CLASSES, HIDDEN,
                                  nullptr, nullptr);
}